// round 8
// baseline (speedup 1.0000x reference)
#include <cuda_runtime.h>
#include <math.h>

#define Bn 64
#define Tn 512
#define En 512
#define Hn 512
#define Kn 12
#define STARTT 10
#define STOPT 11
#define NEGV (-10000.0f)

// ---------------- scratch (device globals; allocation-free rule) ----------------
__device__ float g_pre[2][32768 * 2048];      // [dir][(b*512+t)*2048 + gate*512+j]
__device__ int   g_tok[2][32768];             // [dir][b*512+t]
__device__ float g_h[2][2][Bn * Hn];          // [phase][dir][b*512+j]
__device__ float g_c[2][Bn * Hn];             // [dir][b*512+j]
__device__ float g_outH[33554432];            // [(b*512+t)*1024 + dir*512+j]
__device__ float g_feats[Bn * Tn * Kn];
__device__ signed char g_bp[Bn * Tn * Kn];

// ---------------- init: copy h0/c0 into state buffers ----------------
__global__ void k_init(const float* __restrict__ h0, const float* __restrict__ c0) {
    int i = blockIdx.x * 256 + threadIdx.x;
    if (i < 2 * Bn * Hn) {
        int d = i / (Bn * Hn), r = i % (Bn * Hn);
        g_h[0][d][r] = h0[i];
        g_c[d][r]    = c0[i];
    }
}

// ---------------- token build (forward + packed-reversed; 0 in padding) ----------------
__global__ void k_tok(const int* __restrict__ sent, const int* __restrict__ seq) {
    int i = blockIdx.x * 256 + threadIdx.x;
    if (i >= 2 * 32768) return;
    int d = i >> 15, r = i & 32767, b = r >> 9, t = r & 511;
    int L = seq[b];
    int tk = 0;
    if (t < L) tk = (d == 0) ? sent[b * Tn + t] : sent[b * Tn + (L - 1 - t)];
    g_tok[d][r] = tk;
}

// ---------------- input GEMM: pre = gather(embed, tok) @ Wi^T ----------------
// C tile 64(M) x 64(N), K-tile 16, 256 threads, 4x4 per thread.
__global__ void __launch_bounds__(256) k_gemm(
    const float* __restrict__ embed,
    const float* __restrict__ WiF, const float* __restrict__ WiB,
    const int* __restrict__ seq)
{
    int d  = blockIdx.z;
    int m0 = blockIdx.y * 64;
    int n0 = blockIdx.x * 64;
    int bb = m0 >> 9, t0 = m0 & 511;
    if (t0 >= __ldg(&seq[bb])) return;   // fully-dead tile (seq_lens sorted desc)

    const float* Wi = d ? WiB : WiF;
    __shared__ float As[16][64];
    __shared__ float Bs[16][64];
    __shared__ int   tks[64];

    int tid = threadIdx.x;
    if (tid < 64) tks[tid] = g_tok[d][m0 + tid];
    __syncthreads();

    int ml = tid & 63, kq = tid >> 6;       // loader mapping
    int tx = tid & 15, ty = tid >> 4;       // compute mapping
    float acc[4][4];
#pragma unroll
    for (int i = 0; i < 4; ++i)
#pragma unroll
        for (int j = 0; j < 4; ++j) acc[i][j] = 0.f;

    const float* arow = embed + (size_t)tks[ml] * En;
    const float* brow = Wi + (size_t)(n0 + ml) * En;

    for (int kt = 0; kt < En; kt += 16) {
        float4 a  = *(const float4*)(arow + kt + kq * 4);
        float4 bv = *(const float4*)(brow + kt + kq * 4);
        __syncthreads();
        As[kq * 4 + 0][ml] = a.x;  As[kq * 4 + 1][ml] = a.y;
        As[kq * 4 + 2][ml] = a.z;  As[kq * 4 + 3][ml] = a.w;
        Bs[kq * 4 + 0][ml] = bv.x; Bs[kq * 4 + 1][ml] = bv.y;
        Bs[kq * 4 + 2][ml] = bv.z; Bs[kq * 4 + 3][ml] = bv.w;
        __syncthreads();
#pragma unroll
        for (int k = 0; k < 16; ++k) {
            float4 av = *(const float4*)&As[k][ty * 4];
            float4 bq = *(const float4*)&Bs[k][tx * 4];
            acc[0][0] += av.x * bq.x; acc[0][1] += av.x * bq.y; acc[0][2] += av.x * bq.z; acc[0][3] += av.x * bq.w;
            acc[1][0] += av.y * bq.x; acc[1][1] += av.y * bq.y; acc[1][2] += av.y * bq.z; acc[1][3] += av.y * bq.w;
            acc[2][0] += av.z * bq.x; acc[2][1] += av.z * bq.y; acc[2][2] += av.z * bq.z; acc[2][3] += av.z * bq.w;
            acc[3][0] += av.w * bq.x; acc[3][1] += av.w * bq.y; acc[3][2] += av.w * bq.z; acc[3][3] += av.w * bq.w;
        }
    }
    float* C = g_pre[d] + (size_t)m0 * 2048 + n0;
#pragma unroll
    for (int i = 0; i < 4; ++i) {
        float4 v = make_float4(acc[i][0], acc[i][1], acc[i][2], acc[i][3]);
        *(float4*)(C + (size_t)(ty * 4 + i) * 2048 + tx * 4) = v;
    }
}

// ---------------- one LSTM timestep (both directions), 128 blocks ----------------
// block = (dir, 8 hidden units). thread(tid) = gate-row r=tid>>3 (32 rows: gate*8+jl),
// k-slice ks=tid&7 (64 k each). Wh slice held in registers.
__global__ void __launch_bounds__(256) k_step(
    const float* __restrict__ WhF, const float* __restrict__ WhB,
    const float* __restrict__ bF,  const float* __restrict__ bB,
    const int* __restrict__ seq, int t)
{
    if (t >= __ldg(&seq[0])) return;
    int tid = threadIdx.x;
    int d  = blockIdx.x >> 6;
    int j0 = (blockIdx.x & 63) * 8;
    int r  = tid >> 3, ks = tid & 7;
    int gg = r >> 3,  jl = r & 7;
    int row = gg * 512 + j0 + jl;
    int k0  = ks * 64;

    const float* Whp = (d ? WhB : WhF) + (size_t)row * 512 + k0;
    float4 w[16];
#pragma unroll
    for (int i = 0; i < 16; ++i) w[i] = *(const float4*)(Whp + i * 4);

    // nb = #{b : seq[b] > t}  (sorted desc -> prefix)
    int lo = 0, hi = Bn;
    while (lo < hi) { int mid = (lo + hi) >> 1; if (__ldg(&seq[mid]) > t) lo = mid + 1; else hi = mid; }
    int nb = lo;

    __shared__ float sdots[32][4];
    const float* hbuf  = g_h[t & 1][d];
    float*       hnext = g_h[(t + 1) & 1][d];
    const float* bias  = d ? bB : bF;
    const float* pre   = g_pre[d];

    for (int b0 = 0; b0 < nb; b0 += 4) {
        const float* h0p = hbuf + (b0 + 0) * 512 + k0;
        const float* h1p = hbuf + (b0 + 1 < Bn ? b0 + 1 : Bn - 1) * 512 + k0;
        const float* h2p = hbuf + (b0 + 2 < Bn ? b0 + 2 : Bn - 1) * 512 + k0;
        const float* h3p = hbuf + (b0 + 3 < Bn ? b0 + 3 : Bn - 1) * 512 + k0;
        float a0 = 0.f, a1 = 0.f, a2 = 0.f, a3 = 0.f;
#pragma unroll
        for (int i = 0; i < 16; ++i) {
            float4 wv = w[i];
            float4 v0 = *(const float4*)(h0p + i * 4);
            float4 v1 = *(const float4*)(h1p + i * 4);
            float4 v2 = *(const float4*)(h2p + i * 4);
            float4 v3 = *(const float4*)(h3p + i * 4);
            a0 += wv.x * v0.x + wv.y * v0.y + wv.z * v0.z + wv.w * v0.w;
            a1 += wv.x * v1.x + wv.y * v1.y + wv.z * v1.z + wv.w * v1.w;
            a2 += wv.x * v2.x + wv.y * v2.y + wv.z * v2.z + wv.w * v2.w;
            a3 += wv.x * v3.x + wv.y * v3.y + wv.z * v3.z + wv.w * v3.w;
        }
        // reduce over ks within 8-lane groups
#pragma unroll
        for (int off = 4; off; off >>= 1) {
            a0 += __shfl_down_sync(0xffffffffu, a0, off, 8);
            a1 += __shfl_down_sync(0xffffffffu, a1, off, 8);
            a2 += __shfl_down_sync(0xffffffffu, a2, off, 8);
            a3 += __shfl_down_sync(0xffffffffu, a3, off, 8);
        }
        if (ks == 0) { sdots[r][0] = a0; sdots[r][1] = a1; sdots[r][2] = a2; sdots[r][3] = a3; }
        __syncthreads();

        if (tid < 32) {
            int bi = tid >> 3, jj = tid & 7;
            int b = b0 + bi;
            if (b < nb) {
                int j = j0 + jj;
                size_t pb = (size_t)(b * 512 + t) * 2048 + j;
                float gi = pre[pb +    0] + bias[j]        + sdots[0 * 8 + jj][bi];
                float gf = pre[pb +  512] + bias[512  + j] + sdots[1 * 8 + jj][bi];
                float gc = pre[pb + 1024] + bias[1024 + j] + sdots[2 * 8 + jj][bi];
                float go = pre[pb + 1536] + bias[1536 + j] + sdots[3 * 8 + jj][bi];
                float si = 1.f / (1.f + expf(-gi));
                float sf = 1.f / (1.f + expf(-gf));
                float so = 1.f / (1.f + expf(-go));
                float c  = g_c[d][b * 512 + j];
                float cn = sf * c + si * tanhf(gc);
                float hn = so * tanhf(cn);
                g_c[d][b * 512 + j] = cn;
                hnext[b * 512 + j]  = hn;
                int L = __ldg(&seq[b]);
                int tt = d ? (L - 1 - t) : t;
                g_outH[(size_t)(b * 512 + tt) * 1024 + d * 512 + j] = hn;
            }
        }
        __syncthreads();
    }
}

// ---------------- feats: warp per (b,t), 12 dots of length 1024 ----------------
__global__ void k_feats(const float* __restrict__ Wout, const float* __restrict__ bout,
                        const int* __restrict__ seq)
{
    int gid  = blockIdx.x * 8 + (threadIdx.x >> 5);
    int lane = threadIdx.x & 31;
    int b = gid >> 9, t = gid & 511;
    if (t >= __ldg(&seq[b])) return;
    const float* orow = g_outH + (size_t)gid * 1024;
    float acc[12];
#pragma unroll
    for (int kk = 0; kk < 12; ++kk) acc[kk] = 0.f;
    for (int k = lane * 4; k < 1024; k += 128) {
        float4 o = *(const float4*)(orow + k);
#pragma unroll
        for (int kk = 0; kk < 12; ++kk) {
            float4 wv = *(const float4*)(Wout + kk * 1024 + k);
            acc[kk] += o.x * wv.x + o.y * wv.y + o.z * wv.z + o.w * wv.w;
        }
    }
#pragma unroll
    for (int kk = 0; kk < 12; ++kk) {
        float v = acc[kk];
#pragma unroll
        for (int off = 16; off; off >>= 1) v += __shfl_down_sync(0xffffffffu, v, off);
        if (lane == 0) g_feats[(size_t)gid * 12 + kk] = v + bout[kk];
    }
}

// ---------------- Viterbi: warp per batch row, lane = tag ----------------
__global__ void k_vit(const float* __restrict__ trans, const int* __restrict__ seq,
                      float* __restrict__ out)
{
    int b = blockIdx.x;
    int lane = threadIdx.x;
    int nx = lane < 12 ? lane : 11;
    float tr[12];
#pragma unroll
    for (int p = 0; p < 12; ++p) tr[p] = trans[nx * 12 + p];
    float fv = (lane < 12 && lane == STARTT) ? 0.f : NEGV;
    int L = seq[b];

    for (int t = 0; t < L; ++t) {
        float m = -1e30f; int arg = 0;
#pragma unroll
        for (int p = 0; p < 12; ++p) {
            float fvp = __shfl_sync(0xffffffffu, fv, p);
            float s = fvp + tr[p];
            if (s > m) { m = s; arg = p; }   // first-index argmax (strict >)
        }
        float ft = g_feats[(size_t)(b * 512 + t) * 12 + nx];
        if (lane < 12) {
            fv = m + ft;
            g_bp[(b * 512 + t) * 12 + lane] = (signed char)arg;
        }
    }

    float term = (lane < 12) ? fv + trans[STOPT * 12 + lane] : -1e30f;
    int idx = lane;
#pragma unroll
    for (int off = 16; off; off >>= 1) {
        float ov = __shfl_down_sync(0xffffffffu, term, off);
        int   oi = __shfl_down_sync(0xffffffffu, idx, off);
        if (ov > term || (ov == term && oi < idx)) { term = ov; idx = oi; }
    }
    if (lane == 0) {
        out[b] = term;                      // scores
        int carry = idx;                    // best final tag
        for (int t = Tn - 1; t >= 0; --t) { // emit carry, then step (ident in padding)
            out[64 + b * 512 + t] = (float)carry;
            if (t < L) carry = g_bp[(b * 512 + t) * 12 + carry];
        }
    }
}

// ---------------- launch ----------------
extern "C" void kernel_launch(void* const* d_in, const int* in_sizes, int n_in,
                              void* d_out, int out_size)
{
    const int*   sent  = (const int*)d_in[0];
    const int*   seq   = (const int*)d_in[1];
    const float* embed = (const float*)d_in[2];
    const float* WiF   = (const float*)d_in[3];
    const float* WhF   = (const float*)d_in[4];
    const float* bF    = (const float*)d_in[5];
    const float* WiB   = (const float*)d_in[6];
    const float* WhB   = (const float*)d_in[7];
    const float* bB    = (const float*)d_in[8];
    const float* h0    = (const float*)d_in[9];
    const float* c0    = (const float*)d_in[10];
    const float* Wout  = (const float*)d_in[11];
    const float* bout  = (const float*)d_in[12];
    const float* trans = (const float*)d_in[13];
    float* out = (float*)d_out;

    k_init<<<(2 * Bn * Hn + 255) / 256, 256>>>(h0, c0);
    k_tok<<<(2 * 32768 + 255) / 256, 256>>>(sent, seq);
    dim3 gg(32, 512, 2);
    k_gemm<<<gg, 256>>>(embed, WiF, WiB, seq);
    for (int t = 0; t < Tn; ++t)
        k_step<<<128, 256>>>(WhF, WhB, bF, bB, seq, t);
    k_feats<<<4096, 256>>>(Wout, bout, seq);
    k_vit<<<64, 32>>>(trans, seq, out);
}

// round 10
// speedup vs baseline: 3.7459x; 3.7459x over previous
#include <cuda_runtime.h>
#include <math.h>

#define Bn 64
#define Tn 512
#define En 512
#define Hn 512
#define Kn 12
#define STARTT 10
#define STOPT 11
#define NEGV (-10000.0f)
#define NBLK 128u

// ---------------- scratch (device globals; allocation-free rule) ----------------
__device__ float g_pre[2][32768 * 2048];      // [dir][(b*512+t)*2048 + gate*512+j]
__device__ int   g_tok[2][32768];             // [dir][b*512+t]
__device__ float g_h[2][2][Bn * Hn];          // [phase][dir][b*512+j]
__device__ float g_c[2][Bn * Hn];             // [dir][b*512+j]
__device__ float g_outH[33554432];            // [(b*512+t)*1024 + dir*512+j]
__device__ float g_feats[Bn * Tn * Kn];
__device__ signed char g_bp[Bn * Tn * Kn];
__device__ unsigned g_bar;
__device__ volatile unsigned g_gen;

// ---------------- init ----------------
__global__ void k_init(const float* __restrict__ h0, const float* __restrict__ c0) {
    int i = blockIdx.x * 256 + threadIdx.x;
    if (i == 0) { g_bar = 0u; g_gen = 0u; }
    if (i < 2 * Bn * Hn) {
        int d = i / (Bn * Hn), r = i % (Bn * Hn);
        g_h[0][d][r] = h0[i];
        g_c[d][r]    = c0[i];
    }
}

// ---------------- token build (forward + packed-reversed; 0 in padding) ----------------
__global__ void k_tok(const int* __restrict__ sent, const int* __restrict__ seq) {
    int i = blockIdx.x * 256 + threadIdx.x;
    if (i >= 2 * 32768) return;
    int d = i >> 15, r = i & 32767, b = r >> 9, t = r & 511;
    int L = seq[b];
    int tk = 0;
    if (t < L) tk = (d == 0) ? sent[b * Tn + t] : sent[b * Tn + (L - 1 - t)];
    g_tok[d][r] = tk;
}

// ---------------- input GEMM: pre = gather(embed, tok) @ Wi^T ----------------
__global__ void __launch_bounds__(256) k_gemm(
    const float* __restrict__ embed,
    const float* __restrict__ WiF, const float* __restrict__ WiB,
    const int* __restrict__ seq)
{
    int d  = blockIdx.z;
    int m0 = blockIdx.y * 64;
    int n0 = blockIdx.x * 64;
    int bb = m0 >> 9, t0 = m0 & 511;
    if (t0 >= __ldg(&seq[bb])) return;   // fully-dead tile (seq_lens sorted desc)

    const float* Wi = d ? WiB : WiF;
    __shared__ float As[16][64];
    __shared__ float Bs[16][64];
    __shared__ int   tks[64];

    int tid = threadIdx.x;
    if (tid < 64) tks[tid] = g_tok[d][m0 + tid];
    __syncthreads();

    int ml = tid & 63, kq = tid >> 6;
    int tx = tid & 15, ty = tid >> 4;
    float acc[4][4];
#pragma unroll
    for (int i = 0; i < 4; ++i)
#pragma unroll
        for (int j = 0; j < 4; ++j) acc[i][j] = 0.f;

    const float* arow = embed + (size_t)tks[ml] * En;
    const float* brow = Wi + (size_t)(n0 + ml) * En;

    for (int kt = 0; kt < En; kt += 16) {
        float4 a  = *(const float4*)(arow + kt + kq * 4);
        float4 bv = *(const float4*)(brow + kt + kq * 4);
        __syncthreads();
        As[kq * 4 + 0][ml] = a.x;  As[kq * 4 + 1][ml] = a.y;
        As[kq * 4 + 2][ml] = a.z;  As[kq * 4 + 3][ml] = a.w;
        Bs[kq * 4 + 0][ml] = bv.x; Bs[kq * 4 + 1][ml] = bv.y;
        Bs[kq * 4 + 2][ml] = bv.z; Bs[kq * 4 + 3][ml] = bv.w;
        __syncthreads();
#pragma unroll
        for (int k = 0; k < 16; ++k) {
            float4 av = *(const float4*)&As[k][ty * 4];
            float4 bq = *(const float4*)&Bs[k][tx * 4];
            acc[0][0] += av.x * bq.x; acc[0][1] += av.x * bq.y; acc[0][2] += av.x * bq.z; acc[0][3] += av.x * bq.w;
            acc[1][0] += av.y * bq.x; acc[1][1] += av.y * bq.y; acc[1][2] += av.y * bq.z; acc[1][3] += av.y * bq.w;
            acc[2][0] += av.z * bq.x; acc[2][1] += av.z * bq.y; acc[2][2] += av.z * bq.z; acc[2][3] += av.z * bq.w;
            acc[3][0] += av.w * bq.x; acc[3][1] += av.w * bq.y; acc[3][2] += av.w * bq.z; acc[3][3] += av.w * bq.w;
        }
    }
    float* C = g_pre[d] + (size_t)m0 * 2048 + n0;
#pragma unroll
    for (int i = 0; i < 4; ++i) {
        float4 v = make_float4(acc[i][0], acc[i][1], acc[i][2], acc[i][3]);
        *(float4*)(C + (size_t)(ty * 4 + i) * 2048 + tx * 4) = v;
    }
}

// ---------------- grid barrier (128 co-resident blocks) ----------------
__device__ __forceinline__ void grid_barrier(int tid) {
    __threadfence();
    __syncthreads();
    if (tid == 0) {
        unsigned g = g_gen;
        if (atomicAdd(&g_bar, 1u) == NBLK - 1u) {
            g_bar = 0u;
            __threadfence();
            g_gen = g + 1u;
        } else {
            while (g_gen == g) __nanosleep(64);
        }
    }
    __syncthreads();
}

// ---------------- persistent recurrence: one kernel, all 512 steps ----------------
// block = (dir, 8 hidden units => 32 gate rows). thread = gate-row r=tid>>3,
// k-slice ks=tid&7 with interleaved k = ks*4 + m*32 (conflict-free smem).
// Wh slice lives in registers for the whole kernel.
__global__ void __launch_bounds__(256) k_rec(
    const float* __restrict__ WhF, const float* __restrict__ WhB,
    const float* __restrict__ bF,  const float* __restrict__ bB,
    const int* __restrict__ seq)
{
    int tid = threadIdx.x;
    int d  = blockIdx.x >> 6;
    int j0 = (blockIdx.x & 63) * 8;
    int r  = tid >> 3, ks = tid & 7;
    int gg = r >> 3,  jl = r & 7;
    int row = gg * 512 + j0 + jl;

    const float* Whp = (d ? WhB : WhF) + (size_t)row * 512 + ks * 4;
    float4 w[16];
#pragma unroll
    for (int m = 0; m < 16; ++m) w[m] = *(const float4*)(Whp + m * 32);

    const float* bias = d ? bB : bF;
    const float* pre  = g_pre[d];
    float* cptr = g_c[d];

    __shared__ float sh[8][512];
    __shared__ float sdots[32][8];

    int Lmax = __ldg(&seq[0]);

    for (int t = 0; t < Lmax; ++t) {
        // nb = #{b : seq[b] > t}  (sorted desc -> prefix)
        int lo = 0, hi = Bn;
        while (lo < hi) { int mid = (lo + hi) >> 1; if (__ldg(&seq[mid]) > t) lo = mid + 1; else hi = mid; }
        int nb = lo;

        const float* hbuf  = g_h[t & 1][d];
        float*       hnext = g_h[(t + 1) & 1][d];

        // prefetch tile 0
        float4 pf[4];
#pragma unroll
        for (int p = 0; p < 4; ++p) {
            int q = tid + (p << 8);
            int b = (q >> 7); if (b > 63) b = 63;
            pf[p] = __ldcg((const float4*)(hbuf + b * 512 + ((q & 127) << 2)));
        }

        for (int b0 = 0; b0 < nb; b0 += 8) {
            __syncthreads();   // protect sh/sdots from previous tile's readers
#pragma unroll
            for (int p = 0; p < 4; ++p) {
                int q = tid + (p << 8);
                *(float4*)&sh[q >> 7][(q & 127) << 2] = pf[p];
            }
            __syncthreads();

            // prefetch next tile
            if (b0 + 8 < nb) {
#pragma unroll
                for (int p = 0; p < 4; ++p) {
                    int q = tid + (p << 8);
                    int b = b0 + 8 + (q >> 7); if (b > 63) b = 63;
                    pf[p] = __ldcg((const float4*)(hbuf + b * 512 + ((q & 127) << 2)));
                }
            }

            // 8-batch accumulation from smem (conflict-free)
            float a[8];
#pragma unroll
            for (int bi = 0; bi < 8; ++bi) a[bi] = 0.f;
#pragma unroll
            for (int m = 0; m < 16; ++m) {
                float4 wv = w[m];
                int kk = (ks << 2) + (m << 5);
#pragma unroll
                for (int bi = 0; bi < 8; ++bi) {
                    float4 hv = *(const float4*)&sh[bi][kk];
                    a[bi] += wv.x * hv.x + wv.y * hv.y + wv.z * hv.z + wv.w * hv.w;
                }
            }
            // reduce over ks (8 contiguous lanes)
#pragma unroll
            for (int off = 4; off; off >>= 1)
#pragma unroll
                for (int bi = 0; bi < 8; ++bi)
                    a[bi] += __shfl_down_sync(0xffffffffu, a[bi], off, 8);
            if (ks == 0) {
#pragma unroll
                for (int bi = 0; bi < 8; ++bi) sdots[r][bi] = a[bi];
            }
            __syncthreads();

            // activations: 64 threads = 8 batches x 8 hidden units
            if (tid < 64) {
                int bi = tid >> 3, jj = tid & 7;
                int b = b0 + bi;
                if (b < nb) {
                    int j = j0 + jj;
                    size_t pb = ((size_t)(b << 9) + t) * 2048 + j;
                    float gi = pre[pb +    0] + bias[j]        + sdots[     jj][bi];
                    float gf = pre[pb +  512] + bias[512  + j] + sdots[ 8 + jj][bi];
                    float gc = pre[pb + 1024] + bias[1024 + j] + sdots[16 + jj][bi];
                    float go = pre[pb + 1536] + bias[1536 + j] + sdots[24 + jj][bi];
                    float si = 1.f / (1.f + expf(-gi));
                    float sf = 1.f / (1.f + expf(-gf));
                    float so = 1.f / (1.f + expf(-go));
                    float c  = cptr[(b << 9) + j];
                    float cn = sf * c + si * tanhf(gc);
                    float hn = so * tanhf(cn);
                    cptr[(b << 9) + j] = cn;
                    __stcg(&hnext[(b << 9) + j], hn);
                    int L = __ldg(&seq[b]);
                    int tt = d ? (L - 1 - t) : t;
                    g_outH[((size_t)(b << 9) + tt) * 1024 + (d << 9) + j] = hn;
                }
            }
        }
        grid_barrier(tid);
    }
}

// ---------------- feats: warp per (b,t), 12 dots of length 1024 ----------------
__global__ void k_feats(const float* __restrict__ Wout, const float* __restrict__ bout,
                        const int* __restrict__ seq)
{
    int gid  = blockIdx.x * 8 + (threadIdx.x >> 5);
    int lane = threadIdx.x & 31;
    int b = gid >> 9, t = gid & 511;
    if (t >= __ldg(&seq[b])) return;
    const float* orow = g_outH + (size_t)gid * 1024;
    float acc[12];
#pragma unroll
    for (int kk = 0; kk < 12; ++kk) acc[kk] = 0.f;
    for (int k = lane * 4; k < 1024; k += 128) {
        float4 o = *(const float4*)(orow + k);
#pragma unroll
        for (int kk = 0; kk < 12; ++kk) {
            float4 wv = *(const float4*)(Wout + kk * 1024 + k);
            acc[kk] += o.x * wv.x + o.y * wv.y + o.z * wv.z + o.w * wv.w;
        }
    }
#pragma unroll
    for (int kk = 0; kk < 12; ++kk) {
        float v = acc[kk];
#pragma unroll
        for (int off = 16; off; off >>= 1) v += __shfl_down_sync(0xffffffffu, v, off);
        if (lane == 0) g_feats[(size_t)gid * 12 + kk] = v + bout[kk];
    }
}

// ---------------- Viterbi: warp per batch row, lane = tag ----------------
__global__ void k_vit(const float* __restrict__ trans, const int* __restrict__ seq,
                      float* __restrict__ out)
{
    int b = blockIdx.x;
    int lane = threadIdx.x;
    int nx = lane < 12 ? lane : 11;
    float tr[12];
#pragma unroll
    for (int p = 0; p < 12; ++p) tr[p] = trans[nx * 12 + p];
    float fv = (lane < 12 && lane == STARTT) ? 0.f : NEGV;
    int L = seq[b];

    for (int t = 0; t < L; ++t) {
        float m = -1e30f; int arg = 0;
#pragma unroll
        for (int p = 0; p < 12; ++p) {
            float fvp = __shfl_sync(0xffffffffu, fv, p);
            float s = fvp + tr[p];
            if (s > m) { m = s; arg = p; }   // first-index argmax (strict >)
        }
        float ft = g_feats[(size_t)(b * 512 + t) * 12 + nx];
        if (lane < 12) {
            fv = m + ft;
            g_bp[(b * 512 + t) * 12 + lane] = (signed char)arg;
        }
    }

    float term = (lane < 12) ? fv + trans[STOPT * 12 + lane] : -1e30f;
    int idx = lane;
#pragma unroll
    for (int off = 16; off; off >>= 1) {
        float ov = __shfl_down_sync(0xffffffffu, term, off);
        int   oi = __shfl_down_sync(0xffffffffu, idx, off);
        if (ov > term || (ov == term && oi < idx)) { term = ov; idx = oi; }
    }
    if (lane == 0) {
        out[b] = term;
        int carry = idx;
        for (int t = Tn - 1; t >= 0; --t) {
            out[64 + b * 512 + t] = (float)carry;
            if (t < L) carry = g_bp[(b * 512 + t) * 12 + carry];
        }
    }
}

// ---------------- launch ----------------
extern "C" void kernel_launch(void* const* d_in, const int* in_sizes, int n_in,
                              void* d_out, int out_size)
{
    const int*   sent  = (const int*)d_in[0];
    const int*   seq   = (const int*)d_in[1];
    const float* embed = (const float*)d_in[2];
    const float* WiF   = (const float*)d_in[3];
    const float* WhF   = (const float*)d_in[4];
    const float* bF    = (const float*)d_in[5];
    const float* WiB   = (const float*)d_in[6];
    const float* WhB   = (const float*)d_in[7];
    const float* bB    = (const float*)d_in[8];
    const float* h0    = (const float*)d_in[9];
    const float* c0    = (const float*)d_in[10];
    const float* Wout  = (const float*)d_in[11];
    const float* bout  = (const float*)d_in[12];
    const float* trans = (const float*)d_in[13];
    float* out = (float*)d_out;

    k_init<<<(2 * Bn * Hn + 255) / 256, 256>>>(h0, c0);
    k_tok<<<(2 * 32768 + 255) / 256, 256>>>(sent, seq);
    dim3 gg(32, 512, 2);
    k_gemm<<<gg, 256>>>(embed, WiF, WiB, seq);
    k_rec<<<NBLK, 256>>>(WhF, WhB, bF, bB, seq);
    k_feats<<<4096, 256>>>(Wout, bout, seq);
    k_vit<<<64, 32>>>(trans, seq, out);
}

// round 12
// speedup vs baseline: 4.6702x; 1.2467x over previous
#include <cuda_runtime.h>
#include <math.h>

#define Bn 64
#define Tn 512
#define En 512
#define Hn 512
#define Kn 12
#define STARTT 10
#define STOPT 11
#define NEGV (-10000.0f)

// ---------------- scratch (device globals; allocation-free rule) ----------------
__device__ float g_pre[2][32768 * 2048];      // [dir][(b*512+t)*2048 + gate*512+j]
__device__ int   g_tok[2][32768];             // [dir][b*512+t]
__device__ float g_h[2][2][Bn * Hn];          // [phase][dir][b*512+j]
__device__ float g_c[2][Bn * Hn];             // [dir][b*512+j]
__device__ float g_outH[33554432];            // [(b*512+t)*1024 + dir*512+j]
__device__ float g_feats[Bn * Tn * Kn];
__device__ signed char g_bp[Bn * Tn * Kn];
__device__ unsigned g_ctrs[2][Tn];            // per-(dir,step) arrival counters

// ---------------- init ----------------
__global__ void k_init(const float* __restrict__ h0, const float* __restrict__ c0) {
    int i = blockIdx.x * 256 + threadIdx.x;
    if (i < 2 * Tn) ((unsigned*)g_ctrs)[i] = 0u;
    if (i < 2 * Bn * Hn) {
        int d = i / (Bn * Hn), r = i % (Bn * Hn);
        g_h[0][d][r] = h0[i];
        g_c[d][r]    = c0[i];
    }
}

// ---------------- token build (forward + packed-reversed; 0 in padding) ----------------
__global__ void k_tok(const int* __restrict__ sent, const int* __restrict__ seq) {
    int i = blockIdx.x * 256 + threadIdx.x;
    if (i >= 2 * 32768) return;
    int d = i >> 15, r = i & 32767, b = r >> 9, t = r & 511;
    int L = seq[b];
    int tk = 0;
    if (t < L) tk = (d == 0) ? sent[b * Tn + t] : sent[b * Tn + (L - 1 - t)];
    g_tok[d][r] = tk;
}

// ---------------- input GEMM: pre = gather(embed, tok) @ Wi^T ----------------
__global__ void __launch_bounds__(256) k_gemm(
    const float* __restrict__ embed,
    const float* __restrict__ WiF, const float* __restrict__ WiB,
    const int* __restrict__ seq)
{
    int d  = blockIdx.z;
    int m0 = blockIdx.y * 64;
    int n0 = blockIdx.x * 64;
    int bb = m0 >> 9, t0 = m0 & 511;
    if (t0 >= __ldg(&seq[bb])) return;   // fully-dead tile (seq_lens sorted desc)

    const float* Wi = d ? WiB : WiF;
    __shared__ float As[16][64];
    __shared__ float Bs[16][64];
    __shared__ int   tks[64];

    int tid = threadIdx.x;
    if (tid < 64) tks[tid] = g_tok[d][m0 + tid];
    __syncthreads();

    int ml = tid & 63, kq = tid >> 6;
    int tx = tid & 15, ty = tid >> 4;
    float acc[4][4];
#pragma unroll
    for (int i = 0; i < 4; ++i)
#pragma unroll
        for (int j = 0; j < 4; ++j) acc[i][j] = 0.f;

    const float* arow = embed + (size_t)tks[ml] * En;
    const float* brow = Wi + (size_t)(n0 + ml) * En;

    for (int kt = 0; kt < En; kt += 16) {
        float4 a  = *(const float4*)(arow + kt + kq * 4);
        float4 bv = *(const float4*)(brow + kt + kq * 4);
        __syncthreads();
        As[kq * 4 + 0][ml] = a.x;  As[kq * 4 + 1][ml] = a.y;
        As[kq * 4 + 2][ml] = a.z;  As[kq * 4 + 3][ml] = a.w;
        Bs[kq * 4 + 0][ml] = bv.x; Bs[kq * 4 + 1][ml] = bv.y;
        Bs[kq * 4 + 2][ml] = bv.z; Bs[kq * 4 + 3][ml] = bv.w;
        __syncthreads();
#pragma unroll
        for (int k = 0; k < 16; ++k) {
            float4 av = *(const float4*)&As[k][ty * 4];
            float4 bq = *(const float4*)&Bs[k][tx * 4];
            acc[0][0] += av.x * bq.x; acc[0][1] += av.x * bq.y; acc[0][2] += av.x * bq.z; acc[0][3] += av.x * bq.w;
            acc[1][0] += av.y * bq.x; acc[1][1] += av.y * bq.y; acc[1][2] += av.y * bq.z; acc[1][3] += av.y * bq.w;
            acc[2][0] += av.z * bq.x; acc[2][1] += av.z * bq.y; acc[2][2] += av.z * bq.z; acc[2][3] += av.z * bq.w;
            acc[3][0] += av.w * bq.x; acc[3][1] += av.w * bq.y; acc[3][2] += av.w * bq.z; acc[3][3] += av.w * bq.w;
        }
    }
    float* C = g_pre[d] + (size_t)m0 * 2048 + n0;
#pragma unroll
    for (int i = 0; i < 4; ++i) {
        float4 v = make_float4(acc[i][0], acc[i][1], acc[i][2], acc[i][3]);
        *(float4*)(C + (size_t)(ty * 4 + i) * 2048 + tx * 4) = v;
    }
}

// ---------------- persistent recurrence ----------------
// 128 blocks x 512 threads. block = (dir, 8 hidden units => 32 gate rows).
// thread = (rowpair p=tid>>5 owning rows p and p+16, k-slice lane=tid&31 of 16 k).
// Wh slice (2 rows x 32 floats... 2x16) in registers for the whole kernel.
__global__ void __launch_bounds__(512) k_rec(
    const float* __restrict__ WhF, const float* __restrict__ WhB,
    const float* __restrict__ bF,  const float* __restrict__ bB,
    const int* __restrict__ seq)
{
    int tid = threadIdx.x;
    int d  = blockIdx.x >> 6;
    int j0 = (blockIdx.x & 63) * 8;
    int p    = tid >> 5;
    int lane = tid & 31;
    int g0 = p >> 3, jl = p & 7;
    int wrow0 = g0 * 512 + j0 + jl;           // second row = wrow0 + 1024

    const float* Wh = d ? WhB : WhF;
    float4 w0[4], w1[4];
#pragma unroll
    for (int m = 0; m < 4; ++m) {
        w0[m] = *(const float4*)(Wh + (size_t)wrow0 * 512 + lane * 4 + m * 128);
        w1[m] = *(const float4*)(Wh + (size_t)(wrow0 + 1024) * 512 + lane * 4 + m * 128);
    }

    const float* bias = d ? bB : bF;
    const float* pre  = g_pre[d];
    float* cptr = g_c[d];

    // activation-thread constants (threads 0..63: bi = tid>>3, jj = tid&7)
    int a_jj = tid & 7, a_bi = tid >> 3;
    int a_j  = j0 + a_jj;
    float bz0 = 0.f, bz1 = 0.f, bz2 = 0.f, bz3 = 0.f;
    if (tid < 64) {
        bz0 = __ldg(&bias[a_j]);
        bz1 = __ldg(&bias[512 + a_j]);
        bz2 = __ldg(&bias[1024 + a_j]);
        bz3 = __ldg(&bias[1536 + a_j]);
    }

    __shared__ float sh[8][512];
    __shared__ float sdots[32][8];

    int Lmax = __ldg(&seq[0]);

    for (int t = 0; t < Lmax; ++t) {
        // nb = #{b : seq[b] > t}  (sorted desc -> prefix)
        int lo = 0, hi = Bn;
        while (lo < hi) { int mid = (lo + hi) >> 1; if (__ldg(&seq[mid]) > t) lo = mid + 1; else hi = mid; }
        int nb = lo;

        const float* hbuf  = g_h[t & 1][d];
        float*       hnext = g_h[(t + 1) & 1][d];

        // prefetch tile 0 (2 float4 per thread)
        float4 pf0, pf1;
        {
            int q0 = tid, q1 = tid + 512;
            int b0q = q0 >> 7; if (b0q > 63) b0q = 63;
            int b1q = q1 >> 7; if (b1q > 63) b1q = 63;
            pf0 = __ldcg((const float4*)(hbuf + b0q * 512 + ((q0 & 127) << 2)));
            pf1 = __ldcg((const float4*)(hbuf + b1q * 512 + ((q1 & 127) << 2)));
        }

        for (int b0 = 0; b0 < nb; b0 += 8) {
            __syncthreads();   // previous tile fully consumed
            *(float4*)&sh[(tid) >> 7][((tid) & 127) << 2]        = pf0;
            *(float4*)&sh[(tid + 512) >> 7][((tid + 512) & 127) << 2] = pf1;
            __syncthreads();

            // prefetch next tile
            if (b0 + 8 < nb) {
                int q0 = tid, q1 = tid + 512;
                int bb0 = b0 + 8 + (q0 >> 7); if (bb0 > 63) bb0 = 63;
                int bb1 = b0 + 8 + (q1 >> 7); if (bb1 > 63) bb1 = 63;
                pf0 = __ldcg((const float4*)(hbuf + bb0 * 512 + ((q0 & 127) << 2)));
                pf1 = __ldcg((const float4*)(hbuf + bb1 * 512 + ((q1 & 127) << 2)));
            }

            // prefetch activation inputs (overlaps with compute below)
            float pg0 = 0.f, pg1 = 0.f, pg2 = 0.f, pg3 = 0.f, pc = 0.f;
            bool act = (tid < 64) && (b0 + a_bi < nb);
            int ab = b0 + a_bi;
            if (act) {
                size_t pb = ((size_t)(ab << 9) + t) * 2048 + a_j;
                pg0 = pre[pb];
                pg1 = pre[pb + 512];
                pg2 = pre[pb + 1024];
                pg3 = pre[pb + 1536];
                pc  = cptr[(ab << 9) + a_j];
            }

            // dot products: 2 rows x 8 batches, k-slice of 16 (stride-4 interleave)
            float a0[8], a1[8];
#pragma unroll
            for (int bi = 0; bi < 8; ++bi) { a0[bi] = 0.f; a1[bi] = 0.f; }
#pragma unroll
            for (int m = 0; m < 4; ++m) {
                int kk = (lane << 2) + (m << 7);
                float4 wv0 = w0[m], wv1 = w1[m];
#pragma unroll
                for (int bi = 0; bi < 8; ++bi) {
                    float4 hv = *(const float4*)&sh[bi][kk];
                    a0[bi] += wv0.x * hv.x + wv0.y * hv.y + wv0.z * hv.z + wv0.w * hv.w;
                    a1[bi] += wv1.x * hv.x + wv1.y * hv.y + wv1.z * hv.z + wv1.w * hv.w;
                }
            }
            // full-warp reduce (lane 0 gets sums)
#pragma unroll
            for (int off = 16; off; off >>= 1)
#pragma unroll
                for (int bi = 0; bi < 8; ++bi) {
                    a0[bi] += __shfl_down_sync(0xffffffffu, a0[bi], off);
                    a1[bi] += __shfl_down_sync(0xffffffffu, a1[bi], off);
                }
            if (lane == 0) {
#pragma unroll
                for (int bi = 0; bi < 8; ++bi) {
                    sdots[p][bi]      = a0[bi];
                    sdots[p + 16][bi] = a1[bi];
                }
            }
            __syncthreads();

            // activations: 64 threads = 8 batches x 8 hidden units
            if (act) {
                float gi = pg0 + bz0 + sdots[     a_jj][a_bi];
                float gf = pg1 + bz1 + sdots[ 8 + a_jj][a_bi];
                float gc = pg2 + bz2 + sdots[16 + a_jj][a_bi];
                float go = pg3 + bz3 + sdots[24 + a_jj][a_bi];
                float si = 1.f / (1.f + expf(-gi));
                float sf = 1.f / (1.f + expf(-gf));
                float so = 1.f / (1.f + expf(-go));
                float cn = sf * pc + si * tanhf(gc);
                float hn = so * tanhf(cn);
                cptr[(ab << 9) + a_j] = cn;
                __stcg(&hnext[(ab << 9) + a_j], hn);
                int L = __ldg(&seq[ab]);
                int tt = d ? (L - 1 - t) : t;
                g_outH[((size_t)(ab << 9) + tt) * 1024 + (d << 9) + a_j] = hn;
            }
        }

        // per-dir grid barrier (64 blocks), skipped on the final step
        if (t + 1 < Lmax) {
            __threadfence();
            __syncthreads();
            if (tid == 0) {
                atomicAdd(&g_ctrs[d][t], 1u);
                volatile unsigned* c = &g_ctrs[d][t];
                while (*c < 64u) { }
                __threadfence();
            }
            __syncthreads();
        }
    }
}

// ---------------- feats: warp per (b,t), 12 dots of length 1024 ----------------
__global__ void k_feats(const float* __restrict__ Wout, const float* __restrict__ bout,
                        const int* __restrict__ seq)
{
    int gid  = blockIdx.x * 8 + (threadIdx.x >> 5);
    int lane = threadIdx.x & 31;
    int b = gid >> 9, t = gid & 511;
    if (t >= __ldg(&seq[b])) return;
    const float* orow = g_outH + (size_t)gid * 1024;
    float acc[12];
#pragma unroll
    for (int kk = 0; kk < 12; ++kk) acc[kk] = 0.f;
    for (int k = lane * 4; k < 1024; k += 128) {
        float4 o = *(const float4*)(orow + k);
#pragma unroll
        for (int kk = 0; kk < 12; ++kk) {
            float4 wv = *(const float4*)(Wout + kk * 1024 + k);
            acc[kk] += o.x * wv.x + o.y * wv.y + o.z * wv.z + o.w * wv.w;
        }
    }
#pragma unroll
    for (int kk = 0; kk < 12; ++kk) {
        float v = acc[kk];
#pragma unroll
        for (int off = 16; off; off >>= 1) v += __shfl_down_sync(0xffffffffu, v, off);
        if (lane == 0) g_feats[(size_t)gid * 12 + kk] = v + bout[kk];
    }
}

// ---------------- Viterbi: warp per batch row, lane = tag ----------------
__global__ void k_vit(const float* __restrict__ trans, const int* __restrict__ seq,
                      float* __restrict__ out)
{
    int b = blockIdx.x;
    int lane = threadIdx.x;
    int nx = lane < 12 ? lane : 11;
    float tr[12];
#pragma unroll
    for (int p = 0; p < 12; ++p) tr[p] = trans[nx * 12 + p];
    float fv = (lane < 12 && lane == STARTT) ? 0.f : NEGV;
    int L = seq[b];

    for (int t = 0; t < L; ++t) {
        float m = -1e30f; int arg = 0;
#pragma unroll
        for (int p = 0; p < 12; ++p) {
            float fvp = __shfl_sync(0xffffffffu, fv, p);
            float s = fvp + tr[p];
            if (s > m) { m = s; arg = p; }   // first-index argmax (strict >)
        }
        float ft = g_feats[(size_t)(b * 512 + t) * 12 + nx];
        if (lane < 12) {
            fv = m + ft;
            g_bp[(b * 512 + t) * 12 + lane] = (signed char)arg;
        }
    }

    float term = (lane < 12) ? fv + trans[STOPT * 12 + lane] : -1e30f;
    int idx = lane;
#pragma unroll
    for (int off = 16; off; off >>= 1) {
        float ov = __shfl_down_sync(0xffffffffu, term, off);
        int   oi = __shfl_down_sync(0xffffffffu, idx, off);
        if (ov > term || (ov == term && oi < idx)) { term = ov; idx = oi; }
    }
    if (lane == 0) {
        out[b] = term;
        int carry = idx;
        for (int t = Tn - 1; t >= 0; --t) {
            out[64 + b * 512 + t] = (float)carry;
            if (t < L) carry = g_bp[(b * 512 + t) * 12 + carry];
        }
    }
}

// ---------------- launch ----------------
extern "C" void kernel_launch(void* const* d_in, const int* in_sizes, int n_in,
                              void* d_out, int out_size)
{
    const int*   sent  = (const int*)d_in[0];
    const int*   seq   = (const int*)d_in[1];
    const float* embed = (const float*)d_in[2];
    const float* WiF   = (const float*)d_in[3];
    const float* WhF   = (const float*)d_in[4];
    const float* bF    = (const float*)d_in[5];
    const float* WiB   = (const float*)d_in[6];
    const float* WhB   = (const float*)d_in[7];
    const float* bB    = (const float*)d_in[8];
    const float* h0    = (const float*)d_in[9];
    const float* c0    = (const float*)d_in[10];
    const float* Wout  = (const float*)d_in[11];
    const float* bout  = (const float*)d_in[12];
    const float* trans = (const float*)d_in[13];
    float* out = (float*)d_out;

    k_init<<<(2 * Bn * Hn + 255) / 256, 256>>>(h0, c0);
    k_tok<<<(2 * 32768 + 255) / 256, 256>>>(sent, seq);
    dim3 gg(32, 512, 2);
    k_gemm<<<gg, 256>>>(embed, WiF, WiB, seq);
    k_rec<<<128, 512>>>(WhF, WhB, bF, bB, seq);
    k_feats<<<4096, 256>>>(Wout, bout, seq);
    k_vit<<<64, 32>>>(trans, seq, out);
}

// round 14
// speedup vs baseline: 5.3370x; 1.1428x over previous
#include <cuda_runtime.h>
#include <math.h>

#define Bn 64
#define Tn 512
#define En 512
#define Hn 512
#define Kn 12
#define STARTT 10
#define STOPT 11
#define NEGV (-10000.0f)

// ---------------- scratch (device globals; allocation-free rule) ----------------
__device__ float g_pre[2][32768 * 2048];      // [dir][(b*512+t)*2048 + gate*512+j]
__device__ int   g_tok[2][32768];             // [dir][b*512+t]
__device__ float g_h[2][2][Bn * Hn];          // [phase][dir][b*512+j]
__device__ float g_c[2][Bn * Hn];             // [dir][b*512+j]
__device__ float g_outH[33554432];            // [(b*512+t)*1024 + dir*512+j]
__device__ float g_feats[Bn * Tn * Kn];
__device__ signed char g_bp[Bn * Tn * Kn];
__device__ unsigned g_ctrs[2][Tn];            // per-(dir,step) arrival counters

// ---------------- init ----------------
__global__ void k_init(const float* __restrict__ h0, const float* __restrict__ c0) {
    int i = blockIdx.x * 256 + threadIdx.x;
    if (i < 2 * Tn) ((unsigned*)g_ctrs)[i] = 0u;
    if (i < 2 * Bn * Hn) {
        int d = i / (Bn * Hn), r = i % (Bn * Hn);
        g_h[0][d][r] = h0[i];
        g_c[d][r]    = c0[i];
    }
}

// ---------------- token build (forward + packed-reversed; 0 in padding) ----------------
__global__ void k_tok(const int* __restrict__ sent, const int* __restrict__ seq) {
    int i = blockIdx.x * 256 + threadIdx.x;
    if (i >= 2 * 32768) return;
    int d = i >> 15, r = i & 32767, b = r >> 9, t = r & 511;
    int L = seq[b];
    int tk = 0;
    if (t < L) tk = (d == 0) ? sent[b * Tn + t] : sent[b * Tn + (L - 1 - t)];
    g_tok[d][r] = tk;
}

// ---------------- TF32 helpers ----------------
__device__ __forceinline__ unsigned tf32r(float v) {
    unsigned u;
    asm("cvt.rna.tf32.f32 %0, %1;" : "=r"(u) : "f"(v));
    return u;
}
#define MMA_TF32(c, A, B0, B1)                                                  \
    asm volatile("mma.sync.aligned.m16n8k8.row.col.f32.tf32.tf32.f32 "          \
                 "{%0,%1,%2,%3},{%4,%5,%6,%7},{%8,%9},{%0,%1,%2,%3};"           \
                 : "+f"((c)[0]), "+f"((c)[1]), "+f"((c)[2]), "+f"((c)[3])       \
                 : "r"((A).x), "r"((A).y), "r"((A).z), "r"((A).w),              \
                   "r"(B0), "r"(B1))

// ---------------- input GEMM (TF32 tensor cores): pre = gather(embed, tok) @ Wi^T ----
// Block tile 64(M) x 128(N) x 16(K); 8 warps = 2(M) x 4(N); warp tile 32x32.
// smem holds A/B in per-lane m16n8k8 fragment order (conflict-free LDS in compute).
__global__ void __launch_bounds__(256) k_gemm(
    const float* __restrict__ embed,
    const float* __restrict__ WiF, const float* __restrict__ WiB,
    const int* __restrict__ seq)
{
    int d  = blockIdx.z;
    int m0 = blockIdx.y * 64;
    int n0 = blockIdx.x * 128;
    int bb = m0 >> 9, t0 = m0 & 511;
    if (t0 >= __ldg(&seq[bb])) return;   // fully-dead tile (seq_lens sorted desc)

    const float* Wi = d ? WiB : WiF;

    // As[k8(2)][mt(4)][lane(32)][reg(4)]  Bs[k8(2)][nt(16)][lane(32)][reg(2)]
    __shared__ unsigned As[1024];
    __shared__ unsigned Bs[2048];

    int tid  = threadIdx.x;
    int lane = tid & 31;
    int wid  = tid >> 5;
    int wm   = wid & 1;     // 0..1 (M)
    int wn   = wid >> 1;    // 0..3 (N)

    // A loader: thread -> (m-row am, k-quad aq)
    int am = tid >> 2, aq = tid & 3;
    const float* arow = embed + (size_t)g_tok[d][m0 + am] * 512 + aq * 4;
    // precomputed A scatter offsets (kl&3 = e&3 since aq*4 % 4 == 0)
    int a_mt = am >> 4;
    int a_hi = (am >> 3) & 1;
    int a_ln = (am & 7) << 2;

    // B loader: thread -> (n-row bn, k-half bh)
    int bn = tid >> 1, bh = tid & 1;
    const float* brow = Wi + (size_t)(n0 + bn) * 512 + bh * 8;
    int b_nt = bn >> 3;
    int b_ln = (bn & 7) << 2;

    float acc[2][4][4];
#pragma unroll
    for (int i = 0; i < 2; ++i)
#pragma unroll
        for (int j = 0; j < 4; ++j)
#pragma unroll
            for (int q = 0; q < 4; ++q) acc[i][j][q] = 0.f;

    for (int k0 = 0; k0 < 512; k0 += 16) {
        float4 av  = *(const float4*)(arow + k0);
        float4 bv0 = *(const float4*)(brow + k0);
        float4 bv1 = *(const float4*)(brow + k0 + 4);
        __syncthreads();   // previous compute done
        {
            float v[4] = {av.x, av.y, av.z, av.w};
#pragma unroll
            for (int e = 0; e < 4; ++e) {
                int kk = aq * 4 + e, k8 = kk >> 3, kl = kk & 7;
                int j = ((kl >> 2) << 1) | a_hi;
                As[(((k8 << 2) + a_mt) << 7) + ((a_ln | (e & 3)) << 2) + j] = tf32r(v[e]);
            }
            float w[8] = {bv0.x, bv0.y, bv0.z, bv0.w, bv1.x, bv1.y, bv1.z, bv1.w};
#pragma unroll
            for (int e = 0; e < 8; ++e) {
                Bs[(((bh << 4) + b_nt) << 6) + ((b_ln | (e & 3)) << 1) + (e >> 2)] = tf32r(w[e]);
            }
        }
        __syncthreads();
#pragma unroll
        for (int k8 = 0; k8 < 2; ++k8) {
            uint4 A0 = *(const uint4*)&As[(((k8 << 2) + wm * 2 + 0) << 7) + (lane << 2)];
            uint4 A1 = *(const uint4*)&As[(((k8 << 2) + wm * 2 + 1) << 7) + (lane << 2)];
#pragma unroll
            for (int j = 0; j < 4; ++j) {
                uint2 Bf = *(const uint2*)&Bs[(((k8 << 4) + wn * 4 + j) << 6) + (lane << 1)];
                MMA_TF32(acc[0][j], A0, Bf.x, Bf.y);
                MMA_TF32(acc[1][j], A1, Bf.x, Bf.y);
            }
        }
    }

    // store D: c0,c1 -> (row, col..col+1); c2,c3 -> (row+8, ..)
    float* C = g_pre[d] + (size_t)m0 * 2048 + n0;
#pragma unroll
    for (int i = 0; i < 2; ++i) {
#pragma unroll
        for (int j = 0; j < 4; ++j) {
            int r0 = wm * 32 + i * 16 + (lane >> 2);
            int c0 = wn * 32 + j * 8 + ((lane & 3) << 1);
            *(float2*)(C + (size_t)r0 * 2048 + c0)       = make_float2(acc[i][j][0], acc[i][j][1]);
            *(float2*)(C + (size_t)(r0 + 8) * 2048 + c0) = make_float2(acc[i][j][2], acc[i][j][3]);
        }
    }
}

// ---------------- persistent recurrence ----------------
// 128 blocks x 512 threads. block = (dir, 8 hidden units => 32 gate rows).
// thread = (rowpair p=tid>>5 owning rows p and p+16, k-slice lane=tid&31 of 16 k).
__global__ void __launch_bounds__(512) k_rec(
    const float* __restrict__ WhF, const float* __restrict__ WhB,
    const float* __restrict__ bF,  const float* __restrict__ bB,
    const int* __restrict__ seq)
{
    int tid = threadIdx.x;
    int d  = blockIdx.x >> 6;
    int j0 = (blockIdx.x & 63) * 8;
    int p    = tid >> 5;
    int lane = tid & 31;
    int g0 = p >> 3, jl = p & 7;
    int wrow0 = g0 * 512 + j0 + jl;           // second row = wrow0 + 1024

    const float* Wh = d ? WhB : WhF;
    float4 w0[4], w1[4];
#pragma unroll
    for (int m = 0; m < 4; ++m) {
        w0[m] = *(const float4*)(Wh + (size_t)wrow0 * 512 + lane * 4 + m * 128);
        w1[m] = *(const float4*)(Wh + (size_t)(wrow0 + 1024) * 512 + lane * 4 + m * 128);
    }

    const float* bias = d ? bB : bF;
    const float* pre  = g_pre[d];
    float* cptr = g_c[d];

    int a_jj = tid & 7, a_bi = tid >> 3;
    int a_j  = j0 + a_jj;
    float bz0 = 0.f, bz1 = 0.f, bz2 = 0.f, bz3 = 0.f;
    if (tid < 64) {
        bz0 = __ldg(&bias[a_j]);
        bz1 = __ldg(&bias[512 + a_j]);
        bz2 = __ldg(&bias[1024 + a_j]);
        bz3 = __ldg(&bias[1536 + a_j]);
    }

    __shared__ float sh[8][512];
    __shared__ float sdots[32][8];

    int Lmax = __ldg(&seq[0]);

    for (int t = 0; t < Lmax; ++t) {
        int lo = 0, hi = Bn;
        while (lo < hi) { int mid = (lo + hi) >> 1; if (__ldg(&seq[mid]) > t) lo = mid + 1; else hi = mid; }
        int nb = lo;

        const float* hbuf  = g_h[t & 1][d];
        float*       hnext = g_h[(t + 1) & 1][d];

        float4 pf0, pf1;
        {
            int q0 = tid, q1 = tid + 512;
            int b0q = q0 >> 7; if (b0q > 63) b0q = 63;
            int b1q = q1 >> 7; if (b1q > 63) b1q = 63;
            pf0 = __ldcg((const float4*)(hbuf + b0q * 512 + ((q0 & 127) << 2)));
            pf1 = __ldcg((const float4*)(hbuf + b1q * 512 + ((q1 & 127) << 2)));
        }

        for (int b0 = 0; b0 < nb; b0 += 8) {
            __syncthreads();
            *(float4*)&sh[(tid) >> 7][((tid) & 127) << 2]             = pf0;
            *(float4*)&sh[(tid + 512) >> 7][((tid + 512) & 127) << 2] = pf1;
            __syncthreads();

            if (b0 + 8 < nb) {
                int q0 = tid, q1 = tid + 512;
                int bb0 = b0 + 8 + (q0 >> 7); if (bb0 > 63) bb0 = 63;
                int bb1 = b0 + 8 + (q1 >> 7); if (bb1 > 63) bb1 = 63;
                pf0 = __ldcg((const float4*)(hbuf + bb0 * 512 + ((q0 & 127) << 2)));
                pf1 = __ldcg((const float4*)(hbuf + bb1 * 512 + ((q1 & 127) << 2)));
            }

            float pg0 = 0.f, pg1 = 0.f, pg2 = 0.f, pg3 = 0.f, pc = 0.f;
            bool act = (tid < 64) && (b0 + a_bi < nb);
            int ab = b0 + a_bi;
            if (act) {
                size_t pb = ((size_t)(ab << 9) + t) * 2048 + a_j;
                pg0 = pre[pb];
                pg1 = pre[pb + 512];
                pg2 = pre[pb + 1024];
                pg3 = pre[pb + 1536];
                pc  = cptr[(ab << 9) + a_j];
            }

            float a0[8], a1[8];
#pragma unroll
            for (int bi = 0; bi < 8; ++bi) { a0[bi] = 0.f; a1[bi] = 0.f; }
#pragma unroll
            for (int m = 0; m < 4; ++m) {
                int kk = (lane << 2) + (m << 7);
                float4 wv0 = w0[m], wv1 = w1[m];
#pragma unroll
                for (int bi = 0; bi < 8; ++bi) {
                    float4 hv = *(const float4*)&sh[bi][kk];
                    a0[bi] += wv0.x * hv.x + wv0.y * hv.y + wv0.z * hv.z + wv0.w * hv.w;
                    a1[bi] += wv1.x * hv.x + wv1.y * hv.y + wv1.z * hv.z + wv1.w * hv.w;
                }
            }
#pragma unroll
            for (int off = 16; off; off >>= 1)
#pragma unroll
                for (int bi = 0; bi < 8; ++bi) {
                    a0[bi] += __shfl_down_sync(0xffffffffu, a0[bi], off);
                    a1[bi] += __shfl_down_sync(0xffffffffu, a1[bi], off);
                }
            if (lane == 0) {
#pragma unroll
                for (int bi = 0; bi < 8; ++bi) {
                    sdots[p][bi]      = a0[bi];
                    sdots[p + 16][bi] = a1[bi];
                }
            }
            __syncthreads();

            if (act) {
                float gi = pg0 + bz0 + sdots[     a_jj][a_bi];
                float gf = pg1 + bz1 + sdots[ 8 + a_jj][a_bi];
                float gc = pg2 + bz2 + sdots[16 + a_jj][a_bi];
                float go = pg3 + bz3 + sdots[24 + a_jj][a_bi];
                float si = 1.f / (1.f + expf(-gi));
                float sf = 1.f / (1.f + expf(-gf));
                float so = 1.f / (1.f + expf(-go));
                float cn = sf * pc + si * tanhf(gc);
                float hn = so * tanhf(cn);
                cptr[(ab << 9) + a_j] = cn;
                __stcg(&hnext[(ab << 9) + a_j], hn);
                int L = __ldg(&seq[ab]);
                int tt = d ? (L - 1 - t) : t;
                g_outH[((size_t)(ab << 9) + tt) * 1024 + (d << 9) + a_j] = hn;
            }
        }

        if (t + 1 < Lmax) {
            __threadfence();
            __syncthreads();
            if (tid == 0) {
                atomicAdd(&g_ctrs[d][t], 1u);
                volatile unsigned* c = &g_ctrs[d][t];
                while (*c < 64u) { }
                __threadfence();
            }
            __syncthreads();
        }
    }
}

// ---------------- feats: warp per (b,t), 12 dots of length 1024 ----------------
__global__ void k_feats(const float* __restrict__ Wout, const float* __restrict__ bout,
                        const int* __restrict__ seq)
{
    int gid  = blockIdx.x * 8 + (threadIdx.x >> 5);
    int lane = threadIdx.x & 31;
    int b = gid >> 9, t = gid & 511;
    if (t >= __ldg(&seq[b])) return;
    const float* orow = g_outH + (size_t)gid * 1024;
    float acc[12];
#pragma unroll
    for (int kk = 0; kk < 12; ++kk) acc[kk] = 0.f;
    for (int k = lane * 4; k < 1024; k += 128) {
        float4 o = *(const float4*)(orow + k);
#pragma unroll
        for (int kk = 0; kk < 12; ++kk) {
            float4 wv = *(const float4*)(Wout + kk * 1024 + k);
            acc[kk] += o.x * wv.x + o.y * wv.y + o.z * wv.z + o.w * wv.w;
        }
    }
#pragma unroll
    for (int kk = 0; kk < 12; ++kk) {
        float v = acc[kk];
#pragma unroll
        for (int off = 16; off; off >>= 1) v += __shfl_down_sync(0xffffffffu, v, off);
        if (lane == 0) g_feats[(size_t)gid * 12 + kk] = v + bout[kk];
    }
}

// ---------------- Viterbi: warp per batch row, lane = tag ----------------
__global__ void k_vit(const float* __restrict__ trans, const int* __restrict__ seq,
                      float* __restrict__ out)
{
    int b = blockIdx.x;
    int lane = threadIdx.x;
    int nx = lane < 12 ? lane : 11;
    float tr[12];
#pragma unroll
    for (int p = 0; p < 12; ++p) tr[p] = trans[nx * 12 + p];
    float fv = (lane < 12 && lane == STARTT) ? 0.f : NEGV;
    int L = seq[b];

    for (int t = 0; t < L; ++t) {
        float m = -1e30f; int arg = 0;
#pragma unroll
        for (int p = 0; p < 12; ++p) {
            float fvp = __shfl_sync(0xffffffffu, fv, p);
            float s = fvp + tr[p];
            if (s > m) { m = s; arg = p; }   // first-index argmax (strict >)
        }
        float ft = g_feats[(size_t)(b * 512 + t) * 12 + nx];
        if (lane < 12) {
            fv = m + ft;
            g_bp[(b * 512 + t) * 12 + lane] = (signed char)arg;
        }
    }

    float term = (lane < 12) ? fv + trans[STOPT * 12 + lane] : -1e30f;
    int idx = lane;
#pragma unroll
    for (int off = 16; off; off >>= 1) {
        float ov = __shfl_down_sync(0xffffffffu, term, off);
        int   oi = __shfl_down_sync(0xffffffffu, idx, off);
        if (ov > term || (ov == term && oi < idx)) { term = ov; idx = oi; }
    }
    if (lane == 0) {
        out[b] = term;
        int carry = idx;
        for (int t = Tn - 1; t >= 0; --t) {
            out[64 + b * 512 + t] = (float)carry;
            if (t < L) carry = g_bp[(b * 512 + t) * 12 + carry];
        }
    }
}

// ---------------- launch ----------------
extern "C" void kernel_launch(void* const* d_in, const int* in_sizes, int n_in,
                              void* d_out, int out_size)
{
    const int*   sent  = (const int*)d_in[0];
    const int*   seq   = (const int*)d_in[1];
    const float* embed = (const float*)d_in[2];
    const float* WiF   = (const float*)d_in[3];
    const float* WhF   = (const float*)d_in[4];
    const float* bF    = (const float*)d_in[5];
    const float* WiB   = (const float*)d_in[6];
    const float* WhB   = (const float*)d_in[7];
    const float* bB    = (const float*)d_in[8];
    const float* h0    = (const float*)d_in[9];
    const float* c0    = (const float*)d_in[10];
    const float* Wout  = (const float*)d_in[11];
    const float* bout  = (const float*)d_in[12];
    const float* trans = (const float*)d_in[13];
    float* out = (float*)d_out;

    k_init<<<(2 * Bn * Hn + 255) / 256, 256>>>(h0, c0);
    k_tok<<<(2 * 32768 + 255) / 256, 256>>>(sent, seq);
    dim3 gg(16, 512, 2);
    k_gemm<<<gg, 256>>>(embed, WiF, WiB, seq);
    k_rec<<<128, 512>>>(WhF, WhB, bF, bB, seq);
    k_feats<<<4096, 256>>>(Wout, bout, seq);
    k_vit<<<64, 32>>>(trans, seq, out);
}

// round 15
// speedup vs baseline: 5.6241x; 1.0538x over previous
#include <cuda_runtime.h>
#include <math.h>

#define Bn 64
#define Tn 512
#define En 512
#define Hn 512
#define Kn 12
#define STARTT 10
#define STOPT 11
#define NEGV (-10000.0f)

// ---------------- scratch (device globals; allocation-free rule) ----------------
__device__ float g_pre[2][32768 * 2048];      // [dir][(b*512+t)*2048 + gate*512+j]
__device__ int   g_tok[2][32768];             // [dir][b*512+t]
__device__ float g_h[2][2][Bn * Hn];          // [phase][dir][b*512+j]
__device__ float g_c[2][Bn * Hn];             // [dir][b*512+j]
__device__ float g_outH[33554432];            // [(b*512+t)*1024 + dir*512+j]
__device__ float g_feats[Bn * Tn * Kn];
__device__ signed char g_bp[Bn * Tn * Kn];
__device__ unsigned g_ctrs[2][Tn];            // per-(dir,step) arrival counters

// ---------------- init ----------------
__global__ void k_init(const float* __restrict__ h0, const float* __restrict__ c0) {
    int i = blockIdx.x * 256 + threadIdx.x;
    if (i < 2 * Tn) ((unsigned*)g_ctrs)[i] = 0u;
    if (i < 2 * Bn * Hn) {
        int d = i / (Bn * Hn), r = i % (Bn * Hn);
        g_h[0][d][r] = h0[i];
        g_c[d][r]    = c0[i];
    }
}

// ---------------- token build (forward + packed-reversed; 0 in padding) ----------------
__global__ void k_tok(const int* __restrict__ sent, const int* __restrict__ seq) {
    int i = blockIdx.x * 256 + threadIdx.x;
    if (i >= 2 * 32768) return;
    int d = i >> 15, r = i & 32767, b = r >> 9, t = r & 511;
    int L = seq[b];
    int tk = 0;
    if (t < L) tk = (d == 0) ? sent[b * Tn + t] : sent[b * Tn + (L - 1 - t)];
    g_tok[d][r] = tk;
}

// ---------------- TF32 helpers ----------------
__device__ __forceinline__ unsigned tf32r(float v) {
    unsigned u;
    asm("cvt.rna.tf32.f32 %0, %1;" : "=r"(u) : "f"(v));
    return u;
}
#define MMA_TF32(c, A, B0, B1)                                                  \
    asm volatile("mma.sync.aligned.m16n8k8.row.col.f32.tf32.tf32.f32 "          \
                 "{%0,%1,%2,%3},{%4,%5,%6,%7},{%8,%9},{%0,%1,%2,%3};"           \
                 : "+f"((c)[0]), "+f"((c)[1]), "+f"((c)[2]), "+f"((c)[3])       \
                 : "r"((A).x), "r"((A).y), "r"((A).z), "r"((A).w),              \
                   "r"(B0), "r"(B1))

// packed f32x2 fma: acc(lo,hi) += a(lo,hi) * b(lo,hi)
#define FMA2(acc, a, b) \
    asm("fma.rn.f32x2 %0, %1, %2, %0;" : "+l"(acc) : "l"(a), "l"(b))

__device__ __forceinline__ float fold2(unsigned long long v) {
    return __uint_as_float((unsigned)(v & 0xffffffffu)) +
           __uint_as_float((unsigned)(v >> 32));
}
__device__ __forceinline__ float sigf(float x) {
    return __fdividef(1.f, 1.f + __expf(-x));
}
__device__ __forceinline__ float tanhfa(float x) {
    return 2.f * __fdividef(1.f, 1.f + __expf(-2.f * x)) - 1.f;
}

// ---------------- input GEMM (TF32 tensor cores): pre = gather(embed, tok) @ Wi^T ----
__global__ void __launch_bounds__(256) k_gemm(
    const float* __restrict__ embed,
    const float* __restrict__ WiF, const float* __restrict__ WiB,
    const int* __restrict__ seq)
{
    int d  = blockIdx.z;
    int m0 = blockIdx.y * 64;
    int n0 = blockIdx.x * 128;
    int bb = m0 >> 9, t0 = m0 & 511;
    if (t0 >= __ldg(&seq[bb])) return;   // fully-dead tile (seq_lens sorted desc)

    const float* Wi = d ? WiB : WiF;

    __shared__ unsigned As[1024];
    __shared__ unsigned Bs[2048];

    int tid  = threadIdx.x;
    int lane = tid & 31;
    int wid  = tid >> 5;
    int wm   = wid & 1;
    int wn   = wid >> 1;

    int am = tid >> 2, aq = tid & 3;
    const float* arow = embed + (size_t)g_tok[d][m0 + am] * 512 + aq * 4;
    int a_mt = am >> 4;
    int a_hi = (am >> 3) & 1;
    int a_ln = (am & 7) << 2;

    int bn = tid >> 1, bh = tid & 1;
    const float* brow = Wi + (size_t)(n0 + bn) * 512 + bh * 8;
    int b_nt = bn >> 3;
    int b_ln = (bn & 7) << 2;

    float acc[2][4][4];
#pragma unroll
    for (int i = 0; i < 2; ++i)
#pragma unroll
        for (int j = 0; j < 4; ++j)
#pragma unroll
            for (int q = 0; q < 4; ++q) acc[i][j][q] = 0.f;

    for (int k0 = 0; k0 < 512; k0 += 16) {
        float4 av  = *(const float4*)(arow + k0);
        float4 bv0 = *(const float4*)(brow + k0);
        float4 bv1 = *(const float4*)(brow + k0 + 4);
        __syncthreads();
        {
            float v[4] = {av.x, av.y, av.z, av.w};
#pragma unroll
            for (int e = 0; e < 4; ++e) {
                int kk = aq * 4 + e, k8 = kk >> 3, kl = kk & 7;
                int j = ((kl >> 2) << 1) | a_hi;
                As[(((k8 << 2) + a_mt) << 7) + ((a_ln | (e & 3)) << 2) + j] = tf32r(v[e]);
            }
            float w[8] = {bv0.x, bv0.y, bv0.z, bv0.w, bv1.x, bv1.y, bv1.z, bv1.w};
#pragma unroll
            for (int e = 0; e < 8; ++e) {
                Bs[(((bh << 4) + b_nt) << 6) + ((b_ln | (e & 3)) << 1) + (e >> 2)] = tf32r(w[e]);
            }
        }
        __syncthreads();
#pragma unroll
        for (int k8 = 0; k8 < 2; ++k8) {
            uint4 A0 = *(const uint4*)&As[(((k8 << 2) + wm * 2 + 0) << 7) + (lane << 2)];
            uint4 A1 = *(const uint4*)&As[(((k8 << 2) + wm * 2 + 1) << 7) + (lane << 2)];
#pragma unroll
            for (int j = 0; j < 4; ++j) {
                uint2 Bf = *(const uint2*)&Bs[(((k8 << 4) + wn * 4 + j) << 6) + (lane << 1)];
                MMA_TF32(acc[0][j], A0, Bf.x, Bf.y);
                MMA_TF32(acc[1][j], A1, Bf.x, Bf.y);
            }
        }
    }

    float* C = g_pre[d] + (size_t)m0 * 2048 + n0;
#pragma unroll
    for (int i = 0; i < 2; ++i) {
#pragma unroll
        for (int j = 0; j < 4; ++j) {
            int r0 = wm * 32 + i * 16 + (lane >> 2);
            int c0 = wn * 32 + j * 8 + ((lane & 3) << 1);
            *(float2*)(C + (size_t)r0 * 2048 + c0)       = make_float2(acc[i][j][0], acc[i][j][1]);
            *(float2*)(C + (size_t)(r0 + 8) * 2048 + c0) = make_float2(acc[i][j][2], acc[i][j][3]);
        }
    }
}

// ---------------- persistent recurrence (f32x2 packed FMA) ----------------
// 128 blocks x 512 threads. block = (dir, 8 hidden units => 32 gate rows).
// thread = (rowpair p=tid>>5 owning rows p and p+16, k-slice lane=tid&31 of 16 k).
__global__ void __launch_bounds__(512) k_rec(
    const float* __restrict__ WhF, const float* __restrict__ WhB,
    const float* __restrict__ bF,  const float* __restrict__ bB,
    const int* __restrict__ seq)
{
    int tid = threadIdx.x;
    int d  = blockIdx.x >> 6;
    int j0 = (blockIdx.x & 63) * 8;
    int p    = tid >> 5;
    int lane = tid & 31;
    int g0 = p >> 3, jl = p & 7;
    int wrow0 = g0 * 512 + j0 + jl;           // second row = wrow0 + 1024

    const float* Wh = d ? WhB : WhF;
    // weights as packed f32x2 pairs (bit-identical reinterpretation of float4 loads)
    ulonglong2 w0[4], w1[4];
#pragma unroll
    for (int m = 0; m < 4; ++m) {
        w0[m] = *(const ulonglong2*)(Wh + (size_t)wrow0 * 512 + lane * 4 + m * 128);
        w1[m] = *(const ulonglong2*)(Wh + (size_t)(wrow0 + 1024) * 512 + lane * 4 + m * 128);
    }

    const float* bias = d ? bB : bF;
    const float* pre  = g_pre[d];
    float* cptr = g_c[d];

    int a_jj = tid & 7, a_bi = tid >> 3;
    int a_j  = j0 + a_jj;
    float bz0 = 0.f, bz1 = 0.f, bz2 = 0.f, bz3 = 0.f;
    if (tid < 64) {
        bz0 = __ldg(&bias[a_j]);
        bz1 = __ldg(&bias[512 + a_j]);
        bz2 = __ldg(&bias[1024 + a_j]);
        bz3 = __ldg(&bias[1536 + a_j]);
    }

    __shared__ float sh[8][512];
    __shared__ float sdots[32][8];

    int Lmax = __ldg(&seq[0]);

    for (int t = 0; t < Lmax; ++t) {
        int lo = 0, hi = Bn;
        while (lo < hi) { int mid = (lo + hi) >> 1; if (__ldg(&seq[mid]) > t) lo = mid + 1; else hi = mid; }
        int nb = lo;

        const float* hbuf  = g_h[t & 1][d];
        float*       hnext = g_h[(t + 1) & 1][d];

        float4 pf0, pf1;
        {
            int q0 = tid, q1 = tid + 512;
            int b0q = q0 >> 7; if (b0q > 63) b0q = 63;
            int b1q = q1 >> 7; if (b1q > 63) b1q = 63;
            pf0 = __ldcg((const float4*)(hbuf + b0q * 512 + ((q0 & 127) << 2)));
            pf1 = __ldcg((const float4*)(hbuf + b1q * 512 + ((q1 & 127) << 2)));
        }

        for (int b0 = 0; b0 < nb; b0 += 8) {
            __syncthreads();
            *(float4*)&sh[(tid) >> 7][((tid) & 127) << 2]             = pf0;
            *(float4*)&sh[(tid + 512) >> 7][((tid + 512) & 127) << 2] = pf1;
            __syncthreads();

            if (b0 + 8 < nb) {
                int q0 = tid, q1 = tid + 512;
                int bb0 = b0 + 8 + (q0 >> 7); if (bb0 > 63) bb0 = 63;
                int bb1 = b0 + 8 + (q1 >> 7); if (bb1 > 63) bb1 = 63;
                pf0 = __ldcg((const float4*)(hbuf + bb0 * 512 + ((q0 & 127) << 2)));
                pf1 = __ldcg((const float4*)(hbuf + bb1 * 512 + ((q1 & 127) << 2)));
            }

            float pg0 = 0.f, pg1 = 0.f, pg2 = 0.f, pg3 = 0.f, pc = 0.f;
            bool act = (tid < 64) && (b0 + a_bi < nb);
            int ab = b0 + a_bi;
            if (act) {
                size_t pb = ((size_t)(ab << 9) + t) * 2048 + a_j;
                pg0 = pre[pb];
                pg1 = pre[pb + 512];
                pg2 = pre[pb + 1024];
                pg3 = pre[pb + 1536];
                pc  = cptr[(ab << 9) + a_j];
            }

            // dot products with packed f32x2 FMAs
            unsigned long long c0[8], c1[8];
#pragma unroll
            for (int bi = 0; bi < 8; ++bi) { c0[bi] = 0ull; c1[bi] = 0ull; }
#pragma unroll
            for (int m = 0; m < 4; ++m) {
                int kk = (lane << 2) + (m << 7);
                ulonglong2 wv0 = w0[m], wv1 = w1[m];
#pragma unroll
                for (int bi = 0; bi < 8; ++bi) {
                    ulonglong2 hv = *(const ulonglong2*)&sh[bi][kk];
                    FMA2(c0[bi], wv0.x, hv.x);
                    FMA2(c0[bi], wv0.y, hv.y);
                    FMA2(c1[bi], wv1.x, hv.x);
                    FMA2(c1[bi], wv1.y, hv.y);
                }
            }
            float a0[8], a1[8];
#pragma unroll
            for (int bi = 0; bi < 8; ++bi) { a0[bi] = fold2(c0[bi]); a1[bi] = fold2(c1[bi]); }
#pragma unroll
            for (int off = 16; off; off >>= 1)
#pragma unroll
                for (int bi = 0; bi < 8; ++bi) {
                    a0[bi] += __shfl_down_sync(0xffffffffu, a0[bi], off);
                    a1[bi] += __shfl_down_sync(0xffffffffu, a1[bi], off);
                }
            if (lane == 0) {
#pragma unroll
                for (int bi = 0; bi < 8; ++bi) {
                    sdots[p][bi]      = a0[bi];
                    sdots[p + 16][bi] = a1[bi];
                }
            }
            __syncthreads();

            if (act) {
                float gi = pg0 + bz0 + sdots[     a_jj][a_bi];
                float gf = pg1 + bz1 + sdots[ 8 + a_jj][a_bi];
                float gc = pg2 + bz2 + sdots[16 + a_jj][a_bi];
                float go = pg3 + bz3 + sdots[24 + a_jj][a_bi];
                float si = sigf(gi);
                float sf = sigf(gf);
                float so = sigf(go);
                float cn = sf * pc + si * tanhfa(gc);
                float hn = so * tanhfa(cn);
                cptr[(ab << 9) + a_j] = cn;
                __stcg(&hnext[(ab << 9) + a_j], hn);
                int L = __ldg(&seq[ab]);
                int tt = d ? (L - 1 - t) : t;
                g_outH[((size_t)(ab << 9) + tt) * 1024 + (d << 9) + a_j] = hn;
            }
        }

        if (t + 1 < Lmax) {
            __threadfence();
            __syncthreads();
            if (tid == 0) {
                atomicAdd(&g_ctrs[d][t], 1u);
                volatile unsigned* c = &g_ctrs[d][t];
                while (*c < 64u) { }
                __threadfence();
            }
            __syncthreads();
        }
    }
}

// ---------------- feats: warp per (b,t), 12 dots of length 1024 ----------------
__global__ void k_feats(const float* __restrict__ Wout, const float* __restrict__ bout,
                        const int* __restrict__ seq)
{
    int gid  = blockIdx.x * 8 + (threadIdx.x >> 5);
    int lane = threadIdx.x & 31;
    int b = gid >> 9, t = gid & 511;
    if (t >= __ldg(&seq[b])) return;
    const float* orow = g_outH + (size_t)gid * 1024;
    float acc[12];
#pragma unroll
    for (int kk = 0; kk < 12; ++kk) acc[kk] = 0.f;
    for (int k = lane * 4; k < 1024; k += 128) {
        float4 o = *(const float4*)(orow + k);
#pragma unroll
        for (int kk = 0; kk < 12; ++kk) {
            float4 wv = *(const float4*)(Wout + kk * 1024 + k);
            acc[kk] += o.x * wv.x + o.y * wv.y + o.z * wv.z + o.w * wv.w;
        }
    }
#pragma unroll
    for (int kk = 0; kk < 12; ++kk) {
        float v = acc[kk];
#pragma unroll
        for (int off = 16; off; off >>= 1) v += __shfl_down_sync(0xffffffffu, v, off);
        if (lane == 0) g_feats[(size_t)gid * 12 + kk] = v + bout[kk];
    }
}

// ---------------- Viterbi: warp per batch row, lane = tag ----------------
__global__ void k_vit(const float* __restrict__ trans, const int* __restrict__ seq,
                      float* __restrict__ out)
{
    int b = blockIdx.x;
    int lane = threadIdx.x;
    int nx = lane < 12 ? lane : 11;
    float tr[12];
#pragma unroll
    for (int p = 0; p < 12; ++p) tr[p] = trans[nx * 12 + p];
    float fv = (lane < 12 && lane == STARTT) ? 0.f : NEGV;
    int L = seq[b];

    for (int t = 0; t < L; ++t) {
        float m = -1e30f; int arg = 0;
#pragma unroll
        for (int p = 0; p < 12; ++p) {
            float fvp = __shfl_sync(0xffffffffu, fv, p);
            float s = fvp + tr[p];
            if (s > m) { m = s; arg = p; }   // first-index argmax (strict >)
        }
        float ft = g_feats[(size_t)(b * 512 + t) * 12 + nx];
        if (lane < 12) {
            fv = m + ft;
            g_bp[(b * 512 + t) * 12 + lane] = (signed char)arg;
        }
    }

    float term = (lane < 12) ? fv + trans[STOPT * 12 + lane] : -1e30f;
    int idx = lane;
#pragma unroll
    for (int off = 16; off; off >>= 1) {
        float ov = __shfl_down_sync(0xffffffffu, term, off);
        int   oi = __shfl_down_sync(0xffffffffu, idx, off);
        if (ov > term || (ov == term && oi < idx)) { term = ov; idx = oi; }
    }
    if (lane == 0) {
        out[b] = term;
        int carry = idx;
        for (int t = Tn - 1; t >= 0; --t) {
            out[64 + b * 512 + t] = (float)carry;
            if (t < L) carry = g_bp[(b * 512 + t) * 12 + carry];
        }
    }
}

// ---------------- launch ----------------
extern "C" void kernel_launch(void* const* d_in, const int* in_sizes, int n_in,
                              void* d_out, int out_size)
{
    const int*   sent  = (const int*)d_in[0];
    const int*   seq   = (const int*)d_in[1];
    const float* embed = (const float*)d_in[2];
    const float* WiF   = (const float*)d_in[3];
    const float* WhF   = (const float*)d_in[4];
    const float* bF    = (const float*)d_in[5];
    const float* WiB   = (const float*)d_in[6];
    const float* WhB   = (const float*)d_in[7];
    const float* bB    = (const float*)d_in[8];
    const float* h0    = (const float*)d_in[9];
    const float* c0    = (const float*)d_in[10];
    const float* Wout  = (const float*)d_in[11];
    const float* bout  = (const float*)d_in[12];
    const float* trans = (const float*)d_in[13];
    float* out = (float*)d_out;

    k_init<<<(2 * Bn * Hn + 255) / 256, 256>>>(h0, c0);
    k_tok<<<(2 * 32768 + 255) / 256, 256>>>(sent, seq);
    dim3 gg(16, 512, 2);
    k_gemm<<<gg, 256>>>(embed, WiF, WiB, seq);
    k_rec<<<128, 512>>>(WhF, WhB, bF, bB, seq);
    k_feats<<<4096, 256>>>(Wout, bout, seq);
    k_vit<<<64, 32>>>(trans, seq, out);
}